// round 11
// baseline (speedup 1.0000x reference)
#include <cuda_runtime.h>
#include <math.h>

// GAT_15547781612261 — round 11: gather + GEMM per layer (weights read ~once).

#define NN 8192
#define EE 32768
#define ET (EE + NN)
#define HH 6
#define DCAP 64
#define M1CAP 8192
#define M2CAP 2048

#define C0 1028
#define C1 128
#define C2 256
#define C3 1028
#define W1C 768
#define W2C 1536
#define W3C 6168
#define PITCH1 144      // 128 h1 cols + 6 es2 + 6 ed2, padded
#define PITCH2 272      // 256 h2 cols + 6 es3 + 6 ed3, padded

// ---------------- device globals ----------------
__device__ int fl0[NN], fl1[NN], fl2[NN], fl3[NN];
__device__ int pos1[NN], pos2[NN];
__device__ int lst0[NN], lst1[M1CAP], lst2[M2CAP];
__device__ int g_cnt[4];                 // 0:M1  1:M2  2:M0
__device__ int nodeB[8];
__device__ int deg1[NN], deg2[NN], deg3[NN];
__device__ int bk1[NN * DCAP], bk2[NN * DCAP], bk3[NN * DCAP];
__device__ float es1a[NN * HH], ed1a[NN * HH];
__device__ float p1s[HH * C0], p1d[HH * C0];
__device__ float p2s[HH * C1], p2d[HH * C1];
__device__ float p3s[HH * C2], p3d[HH * C2];
__device__ float r2s[HH * W3C], r2d[HH * W3C];   // logits-B cols for layer-1 gemm
__device__ float r3s[HH * 768], r3d[HH * 768];
__device__ float c2s[HH], c2d[HH], c3s[HH], c3d[HH];
__device__ float agg1[(size_t)M1CAP * W3C];      // [M1, 6168]
__device__ float agg2[(size_t)M2CAP * 768];      // [M2, 768]
__device__ float agg3[8 * 1536];
__device__ float C1g[(size_t)M1CAP * PITCH1];    // h1 | es2 | ed2
__device__ float C2g[(size_t)M2CAP * PITCH2];    // h2 | es3 | ed3

// ================= kA: zero + p-vectors =================
__global__ void kA_init(const float* __restrict__ W1, const float* __restrict__ as1, const float* __restrict__ ad1,
                        const float* __restrict__ W2, const float* __restrict__ as2, const float* __restrict__ ad2,
                        const float* __restrict__ W3, const float* __restrict__ as3, const float* __restrict__ ad3) {
    int tid = blockIdx.x * blockDim.x + threadIdx.x;
    int stride = gridDim.x * blockDim.x;
    for (int i = tid; i < NN; i += stride) {
        fl0[i] = 0; fl1[i] = 0; fl2[i] = 0; fl3[i] = 0;
        deg1[i] = 0; deg2[i] = 0; deg3[i] = 0;
    }
    for (size_t i = tid; i < (size_t)M1CAP * PITCH1; i += stride) C1g[i] = 0.f;
    for (size_t i = tid; i < (size_t)M2CAP * PITCH2; i += stride) C2g[i] = 0.f;
    if (tid < 4) g_cnt[tid] = 0;

    int w = tid >> 5, lane = tid & 31, nw = stride >> 5;
    for (int it = w; it < HH * C0; it += nw) {
        int h = it % HH, k = it / HH;
        const float* wr = W1 + (size_t)k * W1C + h * C1;
        const float* va = as1 + h * C1;
        const float* vd = ad1 + h * C1;
        float ss = 0.f, sd = 0.f;
        #pragma unroll
        for (int j = 0; j < C1 / 32; j++) {
            int c = lane + j * 32;
            float wv = wr[c];
            ss += wv * va[c]; sd += wv * vd[c];
        }
        #pragma unroll
        for (int o = 16; o > 0; o >>= 1) { ss += __shfl_down_sync(~0u, ss, o); sd += __shfl_down_sync(~0u, sd, o); }
        if (lane == 0) { p1s[h * C0 + k] = ss; p1d[h * C0 + k] = sd; }
    }
    for (int it = w; it < HH * C1; it += nw) {
        int h = it % HH, k = it / HH;
        const float* wr = W2 + (size_t)k * W2C + h * C2;
        const float* va = as2 + h * C2;
        const float* vd = ad2 + h * C2;
        float ss = 0.f, sd = 0.f;
        #pragma unroll
        for (int j = 0; j < C2 / 32; j++) {
            int c = lane + j * 32;
            float wv = wr[c];
            ss += wv * va[c]; sd += wv * vd[c];
        }
        #pragma unroll
        for (int o = 16; o > 0; o >>= 1) { ss += __shfl_down_sync(~0u, ss, o); sd += __shfl_down_sync(~0u, sd, o); }
        if (lane == 0) { p2s[h * C1 + k] = ss; p2d[h * C1 + k] = sd; }
    }
    for (int it = w; it < HH * C2; it += nw) {
        int h = it % HH, k = it / HH;
        const float* wr = W3 + (size_t)k * W3C + h * C3;
        const float* va = as3 + h * C3;
        const float* vd = ad3 + h * C3;
        float ss = 0.f, sd = 0.f;
        for (int j = 0; j < 33; j++) {
            int c = lane + j * 32;
            if (c < C3) { float wv = wr[c]; ss += wv * va[c]; sd += wv * vd[c]; }
        }
        #pragma unroll
        for (int o = 16; o > 0; o >>= 1) { ss += __shfl_down_sync(~0u, ss, o); sd += __shfl_down_sync(~0u, sd, o); }
        if (lane == 0) { p3s[h * C2 + k] = ss; p3d[h * C2 + k] = sd; }
    }
}

// ================= kB: single-block BFS + compact + buckets =================
__global__ __launch_bounds__(1024) void kB_graph(const int* __restrict__ ei,
                                                 const int* __restrict__ ptr) {
    int t = threadIdx.x;
    if (t < 8) {
        int node = ptr[t + 1] - 1;
        nodeB[t] = node;
        fl3[node] = 1; fl2[node] = 1; fl1[node] = 1; fl0[node] = 1;
    }
    __syncthreads();
    for (int e = t; e < EE; e += 1024) {
        int d = ei[EE + e];
        if (fl3[d]) { int s = ei[e]; fl2[s] = 1; fl1[s] = 1; fl0[s] = 1; }
    }
    __syncthreads();
    for (int e = t; e < EE; e += 1024) {
        int d = ei[EE + e];
        if (fl2[d]) { int s = ei[e]; fl1[s] = 1; fl0[s] = 1; }
    }
    __syncthreads();
    for (int e = t; e < EE; e += 1024) {
        int d = ei[EE + e];
        if (fl1[d]) fl0[ei[e]] = 1;
    }
    __syncthreads();
    for (int i = t; i < NN; i += 1024) {
        if (fl0[i]) { int j = atomicAdd(&g_cnt[2], 1); lst0[j] = i; }
        if (fl1[i]) { int j = atomicAdd(&g_cnt[0], 1); if (j < M1CAP) { lst1[j] = i; pos1[i] = j; } }
        if (fl2[i]) { int j = atomicAdd(&g_cnt[1], 1); if (j < M2CAP) { lst2[j] = i; pos2[i] = j; } }
    }
    __syncthreads();
    for (int e = t; e < ET; e += 1024) {
        int s, d;
        if (e < EE) { s = ei[e]; d = ei[EE + e]; }
        else        { s = e - EE; d = e - EE; }
        if (fl1[d]) { int j = atomicAdd(&deg1[d], 1); if (j < DCAP) bk1[d * DCAP + j] = s; }
        if (fl2[d]) { int j = atomicAdd(&deg2[d], 1); if (j < DCAP) bk2[d * DCAP + j] = s; }
        if (fl3[d]) { int j = atomicAdd(&deg3[d], 1); if (j < DCAP) bk3[d * DCAP + j] = s; }
    }
}

// ================= kC: r2/r3 + c2/c3 + es1/ed1 + out preload =================
__global__ void kC_prep(const float* __restrict__ x,
                        const float* __restrict__ W1, const float* __restrict__ W2,
                        const float* __restrict__ b1, const float* __restrict__ b2,
                        const float* __restrict__ b3, float* __restrict__ out) {
    int tid = blockIdx.x * blockDim.x + threadIdx.x;
    int stride = gridDim.x * blockDim.x;
    int w = tid >> 5, lane = tid & 31, nw = stride >> 5;

    // out preload: b3 + residual x
    for (int tt = tid; tt < 8 * C3; tt += stride) {
        int b = tt / C3, c = tt - b * C3;
        out[tt] = b3[c] + x[(size_t)nodeB[b] * C0 + c];
    }

    for (int it = w; it < HH * W3C; it += nw) {
        int h2 = it % HH, K = it / HH;
        int head = K / C0, k = K - head * C0;
        const float* wr = W1 + (size_t)k * W1C + head * C1;
        const float* ps = p2s + h2 * C1;
        const float* pd = p2d + h2 * C1;
        float ss = 0.f, sd = 0.f;
        #pragma unroll
        for (int j = 0; j < C1 / 32; j++) {
            int c = lane + j * 32;
            float wv = wr[c];
            ss += wv * ps[c]; sd += wv * pd[c];
        }
        #pragma unroll
        for (int o = 16; o > 0; o >>= 1) { ss += __shfl_down_sync(~0u, ss, o); sd += __shfl_down_sync(~0u, sd, o); }
        if (lane == 0) { r2s[h2 * W3C + K] = ss; r2d[h2 * W3C + K] = sd; }
    }
    for (int it = w; it < HH * 768; it += nw) {
        int h3 = it % HH, K = it / HH;
        int head = K / C1, k = K - head * C1;
        const float* wr = W2 + (size_t)k * W2C + head * C2;
        const float* ps = p3s + h3 * C2;
        const float* pd = p3d + h3 * C2;
        float ss = 0.f, sd = 0.f;
        #pragma unroll
        for (int j = 0; j < C2 / 32; j++) {
            int c = lane + j * 32;
            float wv = wr[c];
            ss += wv * ps[c]; sd += wv * pd[c];
        }
        #pragma unroll
        for (int o = 16; o > 0; o >>= 1) { ss += __shfl_down_sync(~0u, ss, o); sd += __shfl_down_sync(~0u, sd, o); }
        if (lane == 0) { r3s[h3 * 768 + K] = ss; r3d[h3 * 768 + K] = sd; }
    }
    for (int it = w; it < 2 * HH; it += nw) {
        int h = it % HH;
        float ss = 0.f, sd = 0.f;
        if (it < HH) {
            #pragma unroll
            for (int j = 0; j < C1 / 32; j++) {
                int c = lane + j * 32;
                float bb = b1[c];
                ss += bb * p2s[h * C1 + c]; sd += bb * p2d[h * C1 + c];
            }
        } else {
            #pragma unroll
            for (int j = 0; j < C2 / 32; j++) {
                int c = lane + j * 32;
                float bb = b2[c];
                ss += bb * p3s[h * C2 + c]; sd += bb * p3d[h * C2 + c];
            }
        }
        #pragma unroll
        for (int o = 16; o > 0; o >>= 1) { ss += __shfl_down_sync(~0u, ss, o); sd += __shfl_down_sync(~0u, sd, o); }
        if (lane == 0) {
            if (it < HH) { c2s[h] = ss; c2d[h] = sd; }
            else         { c3s[h] = ss; c3d[h] = sd; }
        }
    }
    // es1/ed1 for V0 nodes
    int M0 = g_cnt[2];
    for (int it = w; it < M0 * HH; it += nw) {
        int i = lst0[it / HH], h = it % HH;
        const float* xr = x + (size_t)i * C0;
        const float* ps = p1s + h * C0;
        const float* pd = p1d + h * C0;
        float ss = 0.f, sd = 0.f;
        for (int j = 0; j < 33; j++) {
            int k = lane + j * 32;
            if (k < C0) { float xv = xr[k]; ss += xv * ps[k]; sd += xv * pd[k]; }
        }
        #pragma unroll
        for (int o = 16; o > 0; o >>= 1) { ss += __shfl_down_sync(~0u, ss, o); sd += __shfl_down_sync(~0u, sd, o); }
        if (lane == 0) { es1a[i * HH + h] = ss; ed1a[i * HH + h] = sd; }
    }
}

// ================= gather: block per dst, softmax + write aggcat row =================
__global__ __launch_bounds__(256) void gatherK(int L, const float* __restrict__ x,
                                               const float* __restrict__ b1,
                                               const float* __restrict__ b2) {
    __shared__ float sE[HH][DCAP];
    __shared__ int   sIdx[DCAP];
    __shared__ float sInv[HH];

    int M = (L == 1) ? g_cnt[0] : (L == 2) ? g_cnt[1] : 8;
    if (M > ((L == 1) ? M1CAP : (L == 2) ? M2CAP : 8)) M = (L == 1) ? M1CAP : (L == 2) ? M2CAP : 8;
    int KD = (L == 1) ? C0 : (L == 2) ? C1 : C2;
    float slope = (L == 3) ? 0.f : 0.2f;
    int t = threadIdx.x, w = t >> 5, lane = t & 31;

    for (int i = blockIdx.x; i < M; i += gridDim.x) {
        int node = (L == 1) ? lst1[i] : (L == 2) ? lst2[i] : nodeB[i];
        const int* bk = (L == 1) ? bk1 : (L == 2) ? bk2 : bk3;
        int dg = ((L == 1) ? deg1 : (L == 2) ? deg2 : deg3)[node];
        if (dg > DCAP) dg = DCAP;

        if (w < HH) {
            int h = w;
            float dl;
            if (L == 1)      dl = ed1a[node * HH + h];
            else if (L == 2) dl = C1g[(size_t)pos1[node] * PITCH1 + 134 + h] + c2d[h];
            else             dl = C2g[(size_t)pos2[node] * PITCH2 + 262 + h] + c3d[h];
            float z = 0.f;
            for (int j = lane; j < dg; j += 32) {
                int s = bk[node * DCAP + j];
                int si = (L == 1) ? s : (L == 2) ? pos1[s] : pos2[s];
                if (h == 0) sIdx[j] = si;
                float sl;
                if (L == 1)      sl = es1a[s * HH + h];
                else if (L == 2) sl = C1g[(size_t)si * PITCH1 + 128 + h] + c2s[h];
                else             sl = C2g[(size_t)si * PITCH2 + 256 + h] + c3s[h];
                float v = sl + dl;
                v = (v >= 0.f) ? v : slope * v;
                float e = __expf(v);
                sE[h][j] = e;
                z += e;
            }
            #pragma unroll
            for (int o = 16; o > 0; o >>= 1) z += __shfl_down_sync(~0u, z, o);
            if (lane == 0) sInv[h] = 1.0f / (6.0f * z);
        }
        __syncthreads();

        float* aggrow = (L == 1) ? (agg1 + (size_t)i * W3C)
                      : (L == 2) ? (agg2 + (size_t)i * 768)
                                 : (agg3 + (size_t)i * 1536);
        for (int k = t; k < KD; k += 256) {
            float bias = (L == 1) ? 0.f : (L == 2) ? b1[k] : b2[k];
            float a0 = 0.f, a1 = 0.f, a2 = 0.f, a3 = 0.f, a4 = 0.f, a5 = 0.f;
            for (int j = 0; j < dg; j++) {
                float v;
                if (L == 1)      v = x[(size_t)sIdx[j] * C0 + k];
                else if (L == 2) v = C1g[(size_t)sIdx[j] * PITCH1 + k] + bias;
                else             v = C2g[(size_t)sIdx[j] * PITCH2 + k] + bias;
                a0 += sE[0][j] * v; a1 += sE[1][j] * v; a2 += sE[2][j] * v;
                a3 += sE[3][j] * v; a4 += sE[4][j] * v; a5 += sE[5][j] * v;
            }
            aggrow[0 * KD + k] = a0 * sInv[0];
            aggrow[1 * KD + k] = a1 * sInv[1];
            aggrow[2 * KD + k] = a2 * sInv[2];
            aggrow[3 * KD + k] = a3 * sInv[3];
            aggrow[4 * KD + k] = a4 * sInv[4];
            aggrow[5 * KD + k] = a5 * sInv[5];
        }
        __syncthreads();
    }
}

// ================= gemm: C[M, N] += aggcat[M, Kcat] @ [Wcat | rS | rD] =================
// BM=64, BN=48, BK=16, 256 threads (16x16), 4x3 microtile, K-split via atomicAdd.
__global__ __launch_bounds__(256) void gemmK(int L,
                                             const float* __restrict__ W1,
                                             const float* __restrict__ W2,
                                             const float* __restrict__ W3,
                                             float* __restrict__ out) {
    __shared__ float As[16][65];
    __shared__ float Bs[16][49];

    int M, Kcat, KD, WC, NW, Ncols, PITCH, KS, rStride;
    const float* A; const float* W; float* Cb; const float* rS; const float* rD;
    if (L == 1) {
        M = g_cnt[0]; if (M > M1CAP) M = M1CAP;
        Kcat = W3C; KD = C0; WC = W1C; NW = 128; Ncols = 140; PITCH = PITCH1; KS = 4;
        A = agg1; W = W1; Cb = C1g; rS = r2s; rD = r2d; rStride = W3C;
    } else if (L == 2) {
        M = g_cnt[1]; if (M > M2CAP) M = M2CAP;
        Kcat = 768; KD = C1; WC = W2C; NW = 256; Ncols = 268; PITCH = PITCH2; KS = 4;
        A = agg2; W = W2; Cb = C2g; rS = r3s; rD = r3d; rStride = 768;
    } else {
        M = 8;
        Kcat = 1536; KD = C2; WC = W3C; NW = 1028; Ncols = 1028; PITCH = 1028; KS = 8;
        A = agg3; W = W3; Cb = out; rS = r3s; rD = r3d; rStride = 768;  // r cols unused (Ncols==NW)
    }
    int rt = (M + 63) >> 6;
    int ct = (Ncols + 47) / 48;
    int nIter = (Kcat + 15) >> 4;
    int nt = rt * ct * KS;
    int t = threadIdx.x;
    int ty = t >> 4, tx = t & 15;

    for (int bid = blockIdx.x; bid < nt; bid += gridDim.x) {
        int ksl = bid % KS;
        int rest = bid / KS;
        int ctile = rest % ct, rtile = rest / ct;
        int row0 = rtile * 64, col0 = ctile * 48;
        int it0 = (int)(((long long)nIter * ksl) / KS);
        int it1 = (int)(((long long)nIter * (ksl + 1)) / KS);

        float acc[4][3];
        #pragma unroll
        for (int i = 0; i < 4; i++)
            #pragma unroll
            for (int j = 0; j < 3; j++) acc[i][j] = 0.f;

        for (int it = it0; it < it1; it++) {
            int kbase = it * 16;
            // A tile load: thread -> row t/4, k quad (t%4)*4
            {
                int arow = t >> 2;
                int kq = (t & 3) * 4;
                int grow = row0 + arow;
                #pragma unroll
                for (int u = 0; u < 4; u++) {
                    int k = kbase + kq + u;
                    As[kq + u][arow] = (grow < M && k < Kcat) ? A[(size_t)grow * Kcat + k] : 0.f;
                }
            }
            // B tile load: thread -> k = t/16, cbase = (t%16)*3
            {
                int bk = t >> 4;
                int cb = (t & 15) * 3;
                int K = kbase + bk;
                int head = 0, kk2 = 0;
                if (K < Kcat) { head = K / KD; kk2 = K - head * KD; }
                #pragma unroll
                for (int u = 0; u < 3; u++) {
                    int c = col0 + cb + u;
                    float val = 0.f;
                    if (K < Kcat && c < Ncols) {
                        if (c < NW)            val = W[(size_t)kk2 * WC + head * NW + c];
                        else if (c < NW + 6)   val = rS[(c - NW) * rStride + K];
                        else                   val = rD[(c - NW - 6) * rStride + K];
                    }
                    Bs[bk][cb + u] = val;
                }
            }
            __syncthreads();
            #pragma unroll
            for (int kk = 0; kk < 16; kk++) {
                float a0 = As[kk][ty * 4 + 0];
                float a1 = As[kk][ty * 4 + 1];
                float a2 = As[kk][ty * 4 + 2];
                float a3 = As[kk][ty * 4 + 3];
                float b0 = Bs[kk][tx * 3 + 0];
                float b1v = Bs[kk][tx * 3 + 1];
                float b2v = Bs[kk][tx * 3 + 2];
                acc[0][0] += a0 * b0; acc[0][1] += a0 * b1v; acc[0][2] += a0 * b2v;
                acc[1][0] += a1 * b0; acc[1][1] += a1 * b1v; acc[1][2] += a1 * b2v;
                acc[2][0] += a2 * b0; acc[2][1] += a2 * b1v; acc[2][2] += a2 * b2v;
                acc[3][0] += a3 * b0; acc[3][1] += a3 * b1v; acc[3][2] += a3 * b2v;
            }
            __syncthreads();
        }
        #pragma unroll
        for (int i = 0; i < 4; i++) {
            int r = row0 + ty * 4 + i;
            if (r < M) {
                #pragma unroll
                for (int j = 0; j < 3; j++) {
                    int c = col0 + tx * 3 + j;
                    if (c < Ncols) atomicAdd(&Cb[(size_t)r * PITCH + c], acc[i][j]);
                }
            }
        }
    }
}

// ---------------- launch ----------------
extern "C" void kernel_launch(void* const* d_in, const int* in_sizes, int n_in,
                              void* d_out, int out_size) {
    const float* x   = (const float*)d_in[0];
    const int*   ei  = (const int*)d_in[1];
    const int*   ptr = (const int*)d_in[2];
    const float* W1  = (const float*)d_in[3];
    const float* as1 = (const float*)d_in[4];
    const float* ad1 = (const float*)d_in[5];
    const float* b1  = (const float*)d_in[6];
    const float* W2  = (const float*)d_in[7];
    const float* as2 = (const float*)d_in[8];
    const float* ad2 = (const float*)d_in[9];
    const float* b2  = (const float*)d_in[10];
    const float* W3  = (const float*)d_in[11];
    const float* as3 = (const float*)d_in[12];
    const float* ad3 = (const float*)d_in[13];
    const float* b3  = (const float*)d_in[14];
    float* out = (float*)d_out;

    kA_init<<<512, 256>>>(W1, as1, ad1, W2, as2, ad2, W3, as3, ad3);
    kB_graph<<<1, 1024>>>(ei, ptr);
    kC_prep<<<512, 256>>>(x, W1, W2, b1, b2, b3, out);
    gatherK<<<1024, 256>>>(1, x, b1, b2);
    gemmK<<<512, 256>>>(1, W1, W2, W3, out);
    gatherK<<<512, 256>>>(2, x, b1, b2);
    gemmK<<<256, 256>>>(2, W1, W2, W3, out);
    gatherK<<<16, 256>>>(3, x, b1, b2);
    gemmK<<<256, 256>>>(3, W1, W2, W3, out);
}

// round 13
// speedup vs baseline: 2.3876x; 2.3876x over previous
#include <cuda_runtime.h>
#include <math.h>

// GAT_15547781612261 — round 13 (resubmit of round 12; broker-infra failure, not kernel error).
// Round-7 graph kernels + round-11 gather/GEMM layers.

#define NN 8192
#define EE 32768
#define ET (EE + NN)
#define HH 6
#define DCAP 64
#define M1CAP 8192
#define M2CAP 2048

#define C0 1028
#define C1 128
#define C2 256
#define C3 1028
#define W1C 768
#define W2C 1536
#define W3C 6168
#define PITCH1 144      // 128 h1 cols + 6 es2 + 6 ed2, padded
#define PITCH2 272      // 256 h2 cols + 6 es3 + 6 ed3, padded

// ---------------- device globals ----------------
__device__ int fl0[NN], fl1[NN], fl2[NN], fl3[NN];
__device__ int pos1[NN], pos2[NN];
__device__ int lst1[M1CAP], lst2[M2CAP];
__device__ int g_cnt[4];                 // 0:M1  1:M2
__device__ int nodeB[8];
__device__ int deg1[NN], deg2[NN], deg3[NN];
__device__ int bk1[NN * DCAP], bk2[NN * DCAP], bk3[NN * DCAP];
__device__ float es1a[NN * HH], ed1a[NN * HH];
__device__ float p1s[HH * C0], p1d[HH * C0];
__device__ float p2s[HH * C1], p2d[HH * C1];
__device__ float p3s[HH * C2], p3d[HH * C2];
__device__ float r2s[HH * W3C], r2d[HH * W3C];
__device__ float r3s[HH * 768], r3d[HH * 768];
__device__ float c2s[HH], c2d[HH], c3s[HH], c3d[HH];
__device__ float agg1[(size_t)M1CAP * W3C];
__device__ float agg2[(size_t)M2CAP * 768];
__device__ float agg3[8 * 1536];
__device__ float C1g[(size_t)M1CAP * PITCH1];    // h1 | es2 | ed2
__device__ float C2g[(size_t)M2CAP * PITCH2];    // h2 | es3 | ed3

// ================= k1: zero + p-vectors (warp per dot) =================
__global__ void k1_init(const float* __restrict__ W1, const float* __restrict__ as1, const float* __restrict__ ad1,
                        const float* __restrict__ W2, const float* __restrict__ as2, const float* __restrict__ ad2,
                        const float* __restrict__ W3, const float* __restrict__ as3, const float* __restrict__ ad3) {
    int tid = blockIdx.x * blockDim.x + threadIdx.x;
    int stride = gridDim.x * blockDim.x;
    for (int i = tid; i < NN; i += stride) {
        fl0[i] = 0; fl1[i] = 0; fl2[i] = 0; fl3[i] = 0;
        deg1[i] = 0; deg2[i] = 0; deg3[i] = 0;
    }
    if (tid < 4) g_cnt[tid] = 0;

    int w = tid >> 5, lane = tid & 31, nw = stride >> 5;
    for (int it = w; it < HH * C0; it += nw) {
        int h = it % HH, k = it / HH;
        const float* wr = W1 + (size_t)k * W1C + h * C1;
        const float* va = as1 + h * C1;
        const float* vd = ad1 + h * C1;
        float ss = 0.f, sd = 0.f;
        #pragma unroll
        for (int j = 0; j < C1 / 32; j++) {
            int c = lane + j * 32;
            float wv = wr[c];
            ss += wv * va[c]; sd += wv * vd[c];
        }
        #pragma unroll
        for (int o = 16; o > 0; o >>= 1) { ss += __shfl_down_sync(~0u, ss, o); sd += __shfl_down_sync(~0u, sd, o); }
        if (lane == 0) { p1s[h * C0 + k] = ss; p1d[h * C0 + k] = sd; }
    }
    for (int it = w; it < HH * C1; it += nw) {
        int h = it % HH, k = it / HH;
        const float* wr = W2 + (size_t)k * W2C + h * C2;
        const float* va = as2 + h * C2;
        const float* vd = ad2 + h * C2;
        float ss = 0.f, sd = 0.f;
        #pragma unroll
        for (int j = 0; j < C2 / 32; j++) {
            int c = lane + j * 32;
            float wv = wr[c];
            ss += wv * va[c]; sd += wv * vd[c];
        }
        #pragma unroll
        for (int o = 16; o > 0; o >>= 1) { ss += __shfl_down_sync(~0u, ss, o); sd += __shfl_down_sync(~0u, sd, o); }
        if (lane == 0) { p2s[h * C1 + k] = ss; p2d[h * C1 + k] = sd; }
    }
    for (int it = w; it < HH * C2; it += nw) {
        int h = it % HH, k = it / HH;
        const float* wr = W3 + (size_t)k * W3C + h * C3;
        const float* va = as3 + h * C3;
        const float* vd = ad3 + h * C3;
        float ss = 0.f, sd = 0.f;
        for (int j = 0; j < 33; j++) {
            int c = lane + j * 32;
            if (c < C3) { float wv = wr[c]; ss += wv * va[c]; sd += wv * vd[c]; }
        }
        #pragma unroll
        for (int o = 16; o > 0; o >>= 1) { ss += __shfl_down_sync(~0u, ss, o); sd += __shfl_down_sync(~0u, sd, o); }
        if (lane == 0) { p3s[h * C2 + k] = ss; p3d[h * C2 + k] = sd; }
    }
}

// ================= k2: mark + expand3 + r-vectors =================
__global__ void k2_expand3(const int* __restrict__ ei, const int* __restrict__ ptr,
                           const float* __restrict__ W1, const float* __restrict__ W2,
                           const float* __restrict__ b1, const float* __restrict__ b2) {
    int tid = blockIdx.x * blockDim.x + threadIdx.x;
    int stride = gridDim.x * blockDim.x;
    if (tid < 8) {
        int node = ptr[tid + 1] - 1;
        nodeB[tid] = node;
        fl3[node] = 1; fl2[node] = 1; fl1[node] = 1; fl0[node] = 1;
    }
    int t1 = ptr[1] - 1, t2 = ptr[2] - 1, t3 = ptr[3] - 1, t4 = ptr[4] - 1;
    int t5 = ptr[5] - 1, t6 = ptr[6] - 1, t7 = ptr[7] - 1, t8 = ptr[8] - 1;
    for (int e = tid; e < EE; e += stride) {
        int d = ei[EE + e];
        if (d == t1 || d == t2 || d == t3 || d == t4 || d == t5 || d == t6 || d == t7 || d == t8) {
            int s = ei[e];
            fl2[s] = 1; fl1[s] = 1; fl0[s] = 1;
        }
    }
    int w = tid >> 5, lane = tid & 31, nw = stride >> 5;
    for (int it = w; it < HH * W3C; it += nw) {
        int h2 = it % HH, K = it / HH;
        int head = K / C0, k = K - head * C0;
        const float* wr = W1 + (size_t)k * W1C + head * C1;
        const float* ps = p2s + h2 * C1;
        const float* pd = p2d + h2 * C1;
        float ss = 0.f, sd = 0.f;
        #pragma unroll
        for (int j = 0; j < C1 / 32; j++) {
            int c = lane + j * 32;
            float wv = wr[c];
            ss += wv * ps[c]; sd += wv * pd[c];
        }
        #pragma unroll
        for (int o = 16; o > 0; o >>= 1) { ss += __shfl_down_sync(~0u, ss, o); sd += __shfl_down_sync(~0u, sd, o); }
        if (lane == 0) { r2s[h2 * W3C + K] = ss; r2d[h2 * W3C + K] = sd; }
    }
    for (int it = w; it < HH * 768; it += nw) {
        int h3 = it % HH, K = it / HH;
        int head = K / C1, k = K - head * C1;
        const float* wr = W2 + (size_t)k * W2C + head * C2;
        const float* ps = p3s + h3 * C2;
        const float* pd = p3d + h3 * C2;
        float ss = 0.f, sd = 0.f;
        #pragma unroll
        for (int j = 0; j < C2 / 32; j++) {
            int c = lane + j * 32;
            float wv = wr[c];
            ss += wv * ps[c]; sd += wv * pd[c];
        }
        #pragma unroll
        for (int o = 16; o > 0; o >>= 1) { ss += __shfl_down_sync(~0u, ss, o); sd += __shfl_down_sync(~0u, sd, o); }
        if (lane == 0) { r3s[h3 * 768 + K] = ss; r3d[h3 * 768 + K] = sd; }
    }
    for (int it = w; it < 2 * HH; it += nw) {
        int h = it % HH;
        float ss = 0.f, sd = 0.f;
        if (it < HH) {
            #pragma unroll
            for (int j = 0; j < C1 / 32; j++) {
                int c = lane + j * 32;
                float bb = b1[c];
                ss += bb * p2s[h * C1 + c]; sd += bb * p2d[h * C1 + c];
            }
        } else {
            #pragma unroll
            for (int j = 0; j < C2 / 32; j++) {
                int c = lane + j * 32;
                float bb = b2[c];
                ss += bb * p3s[h * C2 + c]; sd += bb * p3d[h * C2 + c];
            }
        }
        #pragma unroll
        for (int o = 16; o > 0; o >>= 1) { ss += __shfl_down_sync(~0u, ss, o); sd += __shfl_down_sync(~0u, sd, o); }
        if (lane == 0) {
            if (it < HH) { c2s[h] = ss; c2d[h] = sd; }
            else         { c3s[h] = ss; c3d[h] = sd; }
        }
    }
}

// ================= k3/k4: expand =================
__global__ void k3_expand2(const int* __restrict__ ei) {
    int tid = blockIdx.x * blockDim.x + threadIdx.x;
    int stride = gridDim.x * blockDim.x;
    for (int e = tid; e < EE; e += stride) {
        int d = ei[EE + e];
        if (fl2[d]) { int s = ei[e]; fl1[s] = 1; fl0[s] = 1; }
    }
}
__global__ void k4_expand1(const int* __restrict__ ei) {
    int tid = blockIdx.x * blockDim.x + threadIdx.x;
    int stride = gridDim.x * blockDim.x;
    for (int e = tid; e < EE; e += stride) {
        int d = ei[EE + e];
        if (fl1[d]) fl0[ei[e]] = 1;
    }
}

// ================= k5: compact + buckets + es1/ed1 =================
__global__ void k5_build(const int* __restrict__ ei, const float* __restrict__ x) {
    int tid = blockIdx.x * blockDim.x + threadIdx.x;
    int stride = gridDim.x * blockDim.x;
    for (int i = tid; i < NN; i += stride) {
        if (fl1[i]) { int j = atomicAdd(&g_cnt[0], 1); if (j < M1CAP) { lst1[j] = i; pos1[i] = j; } }
        if (fl2[i]) { int j = atomicAdd(&g_cnt[1], 1); if (j < M2CAP) { lst2[j] = i; pos2[i] = j; } }
    }
    for (int t = tid; t < ET; t += stride) {
        int s, d;
        if (t < EE) { s = ei[t]; d = ei[EE + t]; }
        else        { s = t - EE; d = t - EE; }
        if (fl1[d]) { int j = atomicAdd(&deg1[d], 1); if (j < DCAP) bk1[d * DCAP + j] = s; }
        if (fl2[d]) { int j = atomicAdd(&deg2[d], 1); if (j < DCAP) bk2[d * DCAP + j] = s; }
        if (fl3[d]) { int j = atomicAdd(&deg3[d], 1); if (j < DCAP) bk3[d * DCAP + j] = s; }
    }
    int w = tid >> 5, lane = tid & 31, nw = stride >> 5;
    for (int it = w; it < NN * HH; it += nw) {
        int i = it / HH, h = it % HH;
        if (!fl0[i]) continue;
        const float* xr = x + (size_t)i * C0;
        const float* ps = p1s + h * C0;
        const float* pd = p1d + h * C0;
        float ss = 0.f, sd = 0.f;
        for (int j = 0; j < 33; j++) {
            int k = lane + j * 32;
            if (k < C0) { float xv = xr[k]; ss += xv * ps[k]; sd += xv * pd[k]; }
        }
        #pragma unroll
        for (int o = 16; o > 0; o >>= 1) { ss += __shfl_down_sync(~0u, ss, o); sd += __shfl_down_sync(~0u, sd, o); }
        if (lane == 0) { es1a[it] = ss; ed1a[it] = sd; }
    }
}

// ================= gather: block per dst, softmax + write aggcat row =================
// Also zeroes its C row (L1/L2) or preloads out row with b3+residual (L3).
__global__ __launch_bounds__(256) void gatherK(int L, const float* __restrict__ x,
                                               const float* __restrict__ b1,
                                               const float* __restrict__ b2,
                                               const float* __restrict__ b3,
                                               float* __restrict__ out) {
    __shared__ float sE[HH][DCAP];
    __shared__ int   sIdx[DCAP];
    __shared__ float sInv[HH];

    int M = (L == 1) ? g_cnt[0] : (L == 2) ? g_cnt[1] : 8;
    if (M > ((L == 1) ? M1CAP : (L == 2) ? M2CAP : 8)) M = (L == 1) ? M1CAP : (L == 2) ? M2CAP : 8;
    int KD = (L == 1) ? C0 : (L == 2) ? C1 : C2;
    float slope = (L == 3) ? 0.f : 0.2f;
    int t = threadIdx.x, w = t >> 5, lane = t & 31;

    for (int i = blockIdx.x; i < M; i += gridDim.x) {
        if (L == 1) {
            for (int c = t; c < PITCH1; c += 256) C1g[(size_t)i * PITCH1 + c] = 0.f;
        } else if (L == 2) {
            for (int c = t; c < PITCH2; c += 256) C2g[(size_t)i * PITCH2 + c] = 0.f;
        } else {
            int node0 = nodeB[i];
            for (int c = t; c < C3; c += 256)
                out[i * C3 + c] = b3[c] + x[(size_t)node0 * C0 + c];
        }

        int node = (L == 1) ? lst1[i] : (L == 2) ? lst2[i] : nodeB[i];
        const int* bk = (L == 1) ? bk1 : (L == 2) ? bk2 : bk3;
        int dg = ((L == 1) ? deg1 : (L == 2) ? deg2 : deg3)[node];
        if (dg > DCAP) dg = DCAP;

        if (w < HH) {
            int h = w;
            float dl;
            if (L == 1)      dl = ed1a[node * HH + h];
            else if (L == 2) dl = C1g[(size_t)pos1[node] * PITCH1 + 134 + h] + c2d[h];
            else             dl = C2g[(size_t)pos2[node] * PITCH2 + 262 + h] + c3d[h];
            float z = 0.f;
            for (int j = lane; j < dg; j += 32) {
                int s = bk[node * DCAP + j];
                int si = (L == 1) ? s : (L == 2) ? pos1[s] : pos2[s];
                if (h == 0) sIdx[j] = si;
                float sl;
                if (L == 1)      sl = es1a[s * HH + h];
                else if (L == 2) sl = C1g[(size_t)si * PITCH1 + 128 + h] + c2s[h];
                else             sl = C2g[(size_t)si * PITCH2 + 256 + h] + c3s[h];
                float v = sl + dl;
                v = (v >= 0.f) ? v : slope * v;
                float e = __expf(v);
                sE[h][j] = e;
                z += e;
            }
            #pragma unroll
            for (int o = 16; o > 0; o >>= 1) z += __shfl_down_sync(~0u, z, o);
            if (lane == 0) sInv[h] = 1.0f / (6.0f * z);
        }
        __syncthreads();

        float* aggrow = (L == 1) ? (agg1 + (size_t)i * W3C)
                      : (L == 2) ? (agg2 + (size_t)i * 768)
                                 : (agg3 + (size_t)i * 1536);
        for (int k = t; k < KD; k += 256) {
            float bias = (L == 1) ? 0.f : (L == 2) ? b1[k] : b2[k];
            float a0 = 0.f, a1 = 0.f, a2 = 0.f, a3 = 0.f, a4 = 0.f, a5 = 0.f;
            for (int j = 0; j < dg; j++) {
                float v;
                if (L == 1)      v = x[(size_t)sIdx[j] * C0 + k];
                else if (L == 2) v = C1g[(size_t)sIdx[j] * PITCH1 + k] + bias;
                else             v = C2g[(size_t)sIdx[j] * PITCH2 + k] + bias;
                a0 += sE[0][j] * v; a1 += sE[1][j] * v; a2 += sE[2][j] * v;
                a3 += sE[3][j] * v; a4 += sE[4][j] * v; a5 += sE[5][j] * v;
            }
            aggrow[0 * KD + k] = a0 * sInv[0];
            aggrow[1 * KD + k] = a1 * sInv[1];
            aggrow[2 * KD + k] = a2 * sInv[2];
            aggrow[3 * KD + k] = a3 * sInv[3];
            aggrow[4 * KD + k] = a4 * sInv[4];
            aggrow[5 * KD + k] = a5 * sInv[5];
        }
        __syncthreads();
    }
}

// ================= gemm: C[M, N] += aggcat[M, Kcat] @ [Wcat | rS | rD] =================
// BM=64, BN=48, BK=16, 256 threads, 4x3 microtile, K-split via atomicAdd.
__global__ __launch_bounds__(256) void gemmK(int L,
                                             const float* __restrict__ W1,
                                             const float* __restrict__ W2,
                                             const float* __restrict__ W3,
                                             float* __restrict__ out) {
    __shared__ float As[16][65];
    __shared__ float Bs[16][49];

    int M, Kcat, KD, WC, NW, Ncols, PITCH, KS, rStride;
    const float* A; const float* W; float* Cb; const float* rS; const float* rD;
    if (L == 1) {
        M = g_cnt[0]; if (M > M1CAP) M = M1CAP;
        Kcat = W3C; KD = C0; WC = W1C; NW = 128; Ncols = 140; PITCH = PITCH1; KS = 16;
        A = agg1; W = W1; Cb = C1g; rS = r2s; rD = r2d; rStride = W3C;
    } else if (L == 2) {
        M = g_cnt[1]; if (M > M2CAP) M = M2CAP;
        Kcat = 768; KD = C1; WC = W2C; NW = 256; Ncols = 268; PITCH = PITCH2; KS = 8;
        A = agg2; W = W2; Cb = C2g; rS = r3s; rD = r3d; rStride = 768;
    } else {
        M = 8;
        Kcat = 1536; KD = C2; WC = W3C; NW = 1028; Ncols = 1028; PITCH = 1028; KS = 8;
        A = agg3; W = W3; Cb = out; rS = r3s; rD = r3d; rStride = 768;
    }
    int rt = (M + 63) >> 6;
    int ct = (Ncols + 47) / 48;
    int nIter = (Kcat + 15) >> 4;
    int nt = rt * ct * KS;
    int t = threadIdx.x;
    int ty = t >> 4, tx = t & 15;

    for (int bid = blockIdx.x; bid < nt; bid += gridDim.x) {
        int ksl = bid % KS;
        int rest = bid / KS;
        int ctile = rest % ct, rtile = rest / ct;
        int row0 = rtile * 64, col0 = ctile * 48;
        int it0 = (int)(((long long)nIter * ksl) / KS);
        int it1 = (int)(((long long)nIter * (ksl + 1)) / KS);

        float acc[4][3];
        #pragma unroll
        for (int i = 0; i < 4; i++)
            #pragma unroll
            for (int j = 0; j < 3; j++) acc[i][j] = 0.f;

        for (int it = it0; it < it1; it++) {
            int kbase = it * 16;
            {
                int arow = t >> 2;
                int kq = (t & 3) * 4;
                int grow = row0 + arow;
                #pragma unroll
                for (int u = 0; u < 4; u++) {
                    int k = kbase + kq + u;
                    As[kq + u][arow] = (grow < M && k < Kcat) ? A[(size_t)grow * Kcat + k] : 0.f;
                }
            }
            {
                int bk = t >> 4;
                int cb = (t & 15) * 3;
                int K = kbase + bk;
                int head = 0, kk2 = 0;
                if (K < Kcat) { head = K / KD; kk2 = K - head * KD; }
                #pragma unroll
                for (int u = 0; u < 3; u++) {
                    int c = col0 + cb + u;
                    float val = 0.f;
                    if (K < Kcat && c < Ncols) {
                        if (c < NW)            val = W[(size_t)kk2 * WC + head * NW + c];
                        else if (c < NW + 6)   val = rS[(c - NW) * rStride + K];
                        else                   val = rD[(c - NW - 6) * rStride + K];
                    }
                    Bs[bk][cb + u] = val;
                }
            }
            __syncthreads();
            #pragma unroll
            for (int kk = 0; kk < 16; kk++) {
                float a0 = As[kk][ty * 4 + 0];
                float a1 = As[kk][ty * 4 + 1];
                float a2 = As[kk][ty * 4 + 2];
                float a3 = As[kk][ty * 4 + 3];
                float b0 = Bs[kk][tx * 3 + 0];
                float b1v = Bs[kk][tx * 3 + 1];
                float b2v = Bs[kk][tx * 3 + 2];
                acc[0][0] += a0 * b0; acc[0][1] += a0 * b1v; acc[0][2] += a0 * b2v;
                acc[1][0] += a1 * b0; acc[1][1] += a1 * b1v; acc[1][2] += a1 * b2v;
                acc[2][0] += a2 * b0; acc[2][1] += a2 * b1v; acc[2][2] += a2 * b2v;
                acc[3][0] += a3 * b0; acc[3][1] += a3 * b1v; acc[3][2] += a3 * b2v;
            }
            __syncthreads();
        }
        #pragma unroll
        for (int i = 0; i < 4; i++) {
            int r = row0 + ty * 4 + i;
            if (r < M) {
                #pragma unroll
                for (int j = 0; j < 3; j++) {
                    int c = col0 + tx * 3 + j;
                    if (c < Ncols) atomicAdd(&Cb[(size_t)r * PITCH + c], acc[i][j]);
                }
            }
        }
    }
}

// ---------------- launch ----------------
extern "C" void kernel_launch(void* const* d_in, const int* in_sizes, int n_in,
                              void* d_out, int out_size) {
    const float* x   = (const float*)d_in[0];
    const int*   ei  = (const int*)d_in[1];
    const int*   ptr = (const int*)d_in[2];
    const float* W1  = (const float*)d_in[3];
    const float* as1 = (const float*)d_in[4];
    const float* ad1 = (const float*)d_in[5];
    const float* b1  = (const float*)d_in[6];
    const float* W2  = (const float*)d_in[7];
    const float* as2 = (const float*)d_in[8];
    const float* ad2 = (const float*)d_in[9];
    const float* b2  = (const float*)d_in[10];
    const float* W3  = (const float*)d_in[11];
    const float* as3 = (const float*)d_in[12];
    const float* ad3 = (const float*)d_in[13];
    const float* b3  = (const float*)d_in[14];
    float* out = (float*)d_out;

    k1_init<<<512, 256>>>(W1, as1, ad1, W2, as2, ad2, W3, as3, ad3);
    k2_expand3<<<512, 256>>>(ei, ptr, W1, W2, b1, b2);
    k3_expand2<<<128, 256>>>(ei);
    k4_expand1<<<128, 256>>>(ei);
    k5_build<<<2048, 256>>>(ei, x);
    gatherK<<<512, 256>>>(1, x, b1, b2, b3, out);
    gemmK<<<192, 256>>>(1, W1, W2, W3, out);
    gatherK<<<64, 256>>>(2, x, b1, b2, b3, out);
    gemmK<<<64, 256>>>(2, W1, W2, W3, out);
    gatherK<<<16, 256>>>(3, x, b1, b2, b3, out);
    gemmK<<<192, 256>>>(3, W1, W2, W3, out);
}

// round 15
// speedup vs baseline: 2.4756x; 1.0368x over previous
#include <cuda_runtime.h>
#include <math.h>

// GAT_15547781612261 — round 15 (resubmit of round 14; broker-infra failure).
// 10 kernels; logits-in-gather (no fl0/k4), once-read r-vectors, float4 gather.

#define NN 8192
#define EE 32768
#define ET (EE + NN)
#define HH 6
#define DCAP 64
#define M1CAP 8192
#define M2CAP 2048

#define C0 1028
#define C1 128
#define C2 256
#define C3 1028
#define W1C 768
#define W2C 1536
#define W3C 6168
#define PITCH1 144
#define PITCH2 272

// ---------------- device globals ----------------
__device__ int fl1[NN], fl2[NN], fl3[NN];
__device__ int pos1[NN], pos2[NN];
__device__ int lst1[M1CAP], lst2[M2CAP];
__device__ int g_cnt[4];
__device__ int nodeB[8];
__device__ int deg1[NN], deg2[NN], deg3[NN];
__device__ int bk1[NN * DCAP], bk2[NN * DCAP], bk3[NN * DCAP];
__device__ float p1s[HH * C0], p1d[HH * C0];
__device__ float p2s[HH * C1], p2d[HH * C1];
__device__ float p3s[HH * C2], p3d[HH * C2];
__device__ float r2s[HH * W3C], r2d[HH * W3C];
__device__ float r3s[HH * 768], r3d[HH * 768];
__device__ float c2s[HH], c2d[HH], c3s[HH], c3d[HH];
__device__ float agg1[(size_t)M1CAP * W3C];
__device__ float agg2[(size_t)M2CAP * 768];
__device__ float agg3[8 * 1536];
__device__ float C1g[(size_t)M1CAP * PITCH1];    // h1 | es2 | ed2
__device__ float C2g[(size_t)M2CAP * PITCH2];    // h2 | es3 | ed3

// ================= k1: zero + p-vectors =================
__global__ void k1_init(const float* __restrict__ W1, const float* __restrict__ as1, const float* __restrict__ ad1,
                        const float* __restrict__ W2, const float* __restrict__ as2, const float* __restrict__ ad2,
                        const float* __restrict__ W3, const float* __restrict__ as3, const float* __restrict__ ad3) {
    int tid = blockIdx.x * blockDim.x + threadIdx.x;
    int stride = gridDim.x * blockDim.x;
    for (int i = tid; i < NN; i += stride) {
        fl1[i] = 0; fl2[i] = 0; fl3[i] = 0;
        deg1[i] = 0; deg2[i] = 0; deg3[i] = 0;
    }
    if (tid < 4) g_cnt[tid] = 0;

    int w = tid >> 5, lane = tid & 31, nw = stride >> 5;
    for (int it = w; it < HH * C0; it += nw) {
        int h = it % HH, k = it / HH;
        const float* wr = W1 + (size_t)k * W1C + h * C1;
        const float* va = as1 + h * C1;
        const float* vd = ad1 + h * C1;
        float ss = 0.f, sd = 0.f;
        #pragma unroll
        for (int j = 0; j < C1 / 32; j++) {
            int c = lane + j * 32;
            float wv = wr[c];
            ss += wv * va[c]; sd += wv * vd[c];
        }
        #pragma unroll
        for (int o = 16; o > 0; o >>= 1) { ss += __shfl_down_sync(~0u, ss, o); sd += __shfl_down_sync(~0u, sd, o); }
        if (lane == 0) { p1s[h * C0 + k] = ss; p1d[h * C0 + k] = sd; }
    }
    for (int it = w; it < HH * C1; it += nw) {
        int h = it % HH, k = it / HH;
        const float* wr = W2 + (size_t)k * W2C + h * C2;
        const float* va = as2 + h * C2;
        const float* vd = ad2 + h * C2;
        float ss = 0.f, sd = 0.f;
        #pragma unroll
        for (int j = 0; j < C2 / 32; j++) {
            int c = lane + j * 32;
            float wv = wr[c];
            ss += wv * va[c]; sd += wv * vd[c];
        }
        #pragma unroll
        for (int o = 16; o > 0; o >>= 1) { ss += __shfl_down_sync(~0u, ss, o); sd += __shfl_down_sync(~0u, sd, o); }
        if (lane == 0) { p2s[h * C1 + k] = ss; p2d[h * C1 + k] = sd; }
    }
    for (int it = w; it < HH * C2; it += nw) {
        int h = it % HH, k = it / HH;
        const float* wr = W3 + (size_t)k * W3C + h * C3;
        const float* va = as3 + h * C3;
        const float* vd = ad3 + h * C3;
        float ss = 0.f, sd = 0.f;
        for (int j = 0; j < 33; j++) {
            int c = lane + j * 32;
            if (c < C3) { float wv = wr[c]; ss += wv * va[c]; sd += wv * vd[c]; }
        }
        #pragma unroll
        for (int o = 16; o > 0; o >>= 1) { ss += __shfl_down_sync(~0u, ss, o); sd += __shfl_down_sync(~0u, sd, o); }
        if (lane == 0) { p3s[h * C2 + k] = ss; p3d[h * C2 + k] = sd; }
    }
}

// ================= k2: mark + expand3 + r-vectors (W read once) =================
__global__ void k2_expand3(const int* __restrict__ ei, const int* __restrict__ ptr,
                           const float* __restrict__ W1, const float* __restrict__ W2,
                           const float* __restrict__ b1, const float* __restrict__ b2) {
    int tid = blockIdx.x * blockDim.x + threadIdx.x;
    int stride = gridDim.x * blockDim.x;
    if (tid < 8) {
        int node = ptr[tid + 1] - 1;
        nodeB[tid] = node;
        fl3[node] = 1; fl2[node] = 1; fl1[node] = 1;
    }
    int t1 = ptr[1] - 1, t2 = ptr[2] - 1, t3 = ptr[3] - 1, t4 = ptr[4] - 1;
    int t5 = ptr[5] - 1, t6 = ptr[6] - 1, t7 = ptr[7] - 1, t8 = ptr[8] - 1;
    for (int e = tid; e < EE; e += stride) {
        int d = ei[EE + e];
        if (d == t1 || d == t2 || d == t3 || d == t4 || d == t5 || d == t6 || d == t7 || d == t8) {
            int s = ei[e];
            fl2[s] = 1; fl1[s] = 1;
        }
    }
    int w = tid >> 5, lane = tid & 31, nw = stride >> 5;
    // r2[h2, K]: one warp per K, all 6 h2 at once
    for (int K = w; K < W3C; K += nw) {
        int head = K / C0, k = K - head * C0;
        const float* wr = W1 + (size_t)k * W1C + head * C1;
        float ss0 = 0.f, ss1 = 0.f, ss2 = 0.f, ss3 = 0.f, ss4 = 0.f, ss5 = 0.f;
        float dd0 = 0.f, dd1 = 0.f, dd2 = 0.f, dd3 = 0.f, dd4 = 0.f, dd5 = 0.f;
        #pragma unroll
        for (int j = 0; j < C1 / 32; j++) {
            int c = lane + j * 32;
            float wv = wr[c];
            ss0 += wv * p2s[0 * C1 + c]; dd0 += wv * p2d[0 * C1 + c];
            ss1 += wv * p2s[1 * C1 + c]; dd1 += wv * p2d[1 * C1 + c];
            ss2 += wv * p2s[2 * C1 + c]; dd2 += wv * p2d[2 * C1 + c];
            ss3 += wv * p2s[3 * C1 + c]; dd3 += wv * p2d[3 * C1 + c];
            ss4 += wv * p2s[4 * C1 + c]; dd4 += wv * p2d[4 * C1 + c];
            ss5 += wv * p2s[5 * C1 + c]; dd5 += wv * p2d[5 * C1 + c];
        }
        #pragma unroll
        for (int o = 16; o > 0; o >>= 1) {
            ss0 += __shfl_down_sync(~0u, ss0, o); dd0 += __shfl_down_sync(~0u, dd0, o);
            ss1 += __shfl_down_sync(~0u, ss1, o); dd1 += __shfl_down_sync(~0u, dd1, o);
            ss2 += __shfl_down_sync(~0u, ss2, o); dd2 += __shfl_down_sync(~0u, dd2, o);
            ss3 += __shfl_down_sync(~0u, ss3, o); dd3 += __shfl_down_sync(~0u, dd3, o);
            ss4 += __shfl_down_sync(~0u, ss4, o); dd4 += __shfl_down_sync(~0u, dd4, o);
            ss5 += __shfl_down_sync(~0u, ss5, o); dd5 += __shfl_down_sync(~0u, dd5, o);
        }
        if (lane == 0) {
            r2s[0 * W3C + K] = ss0; r2d[0 * W3C + K] = dd0;
            r2s[1 * W3C + K] = ss1; r2d[1 * W3C + K] = dd1;
            r2s[2 * W3C + K] = ss2; r2d[2 * W3C + K] = dd2;
            r2s[3 * W3C + K] = ss3; r2d[3 * W3C + K] = dd3;
            r2s[4 * W3C + K] = ss4; r2d[4 * W3C + K] = dd4;
            r2s[5 * W3C + K] = ss5; r2d[5 * W3C + K] = dd5;
        }
    }
    // r3[h3, K]: one warp per K
    for (int K = w; K < 768; K += nw) {
        int head = K / C1, k = K - head * C1;
        const float* wr = W2 + (size_t)k * W2C + head * C2;
        float ss0 = 0.f, ss1 = 0.f, ss2 = 0.f, ss3 = 0.f, ss4 = 0.f, ss5 = 0.f;
        float dd0 = 0.f, dd1 = 0.f, dd2 = 0.f, dd3 = 0.f, dd4 = 0.f, dd5 = 0.f;
        #pragma unroll
        for (int j = 0; j < C2 / 32; j++) {
            int c = lane + j * 32;
            float wv = wr[c];
            ss0 += wv * p3s[0 * C2 + c]; dd0 += wv * p3d[0 * C2 + c];
            ss1 += wv * p3s[1 * C2 + c]; dd1 += wv * p3d[1 * C2 + c];
            ss2 += wv * p3s[2 * C2 + c]; dd2 += wv * p3d[2 * C2 + c];
            ss3 += wv * p3s[3 * C2 + c]; dd3 += wv * p3d[3 * C2 + c];
            ss4 += wv * p3s[4 * C2 + c]; dd4 += wv * p3d[4 * C2 + c];
            ss5 += wv * p3s[5 * C2 + c]; dd5 += wv * p3d[5 * C2 + c];
        }
        #pragma unroll
        for (int o = 16; o > 0; o >>= 1) {
            ss0 += __shfl_down_sync(~0u, ss0, o); dd0 += __shfl_down_sync(~0u, dd0, o);
            ss1 += __shfl_down_sync(~0u, ss1, o); dd1 += __shfl_down_sync(~0u, dd1, o);
            ss2 += __shfl_down_sync(~0u, ss2, o); dd2 += __shfl_down_sync(~0u, dd2, o);
            ss3 += __shfl_down_sync(~0u, ss3, o); dd3 += __shfl_down_sync(~0u, dd3, o);
            ss4 += __shfl_down_sync(~0u, ss4, o); dd4 += __shfl_down_sync(~0u, dd4, o);
            ss5 += __shfl_down_sync(~0u, ss5, o); dd5 += __shfl_down_sync(~0u, dd5, o);
        }
        if (lane == 0) {
            r3s[0 * 768 + K] = ss0; r3d[0 * 768 + K] = dd0;
            r3s[1 * 768 + K] = ss1; r3d[1 * 768 + K] = dd1;
            r3s[2 * 768 + K] = ss2; r3d[2 * 768 + K] = dd2;
            r3s[3 * 768 + K] = ss3; r3d[3 * 768 + K] = dd3;
            r3s[4 * 768 + K] = ss4; r3d[4 * 768 + K] = dd4;
            r3s[5 * 768 + K] = ss5; r3d[5 * 768 + K] = dd5;
        }
    }
    for (int it = w; it < 2 * HH; it += nw) {
        int h = it % HH;
        float ss = 0.f, sd = 0.f;
        if (it < HH) {
            #pragma unroll
            for (int j = 0; j < C1 / 32; j++) {
                int c = lane + j * 32;
                float bb = b1[c];
                ss += bb * p2s[h * C1 + c]; sd += bb * p2d[h * C1 + c];
            }
        } else {
            #pragma unroll
            for (int j = 0; j < C2 / 32; j++) {
                int c = lane + j * 32;
                float bb = b2[c];
                ss += bb * p3s[h * C2 + c]; sd += bb * p3d[h * C2 + c];
            }
        }
        #pragma unroll
        for (int o = 16; o > 0; o >>= 1) { ss += __shfl_down_sync(~0u, ss, o); sd += __shfl_down_sync(~0u, sd, o); }
        if (lane == 0) {
            if (it < HH) { c2s[h] = ss; c2d[h] = sd; }
            else         { c3s[h] = ss; c3d[h] = sd; }
        }
    }
}

// ================= k3: expand level 2 =================
__global__ void k3_expand2(const int* __restrict__ ei) {
    int tid = blockIdx.x * blockDim.x + threadIdx.x;
    int stride = gridDim.x * blockDim.x;
    for (int e = tid; e < EE; e += stride) {
        int d = ei[EE + e];
        if (fl2[d]) fl1[ei[e]] = 1;
    }
}

// ================= k5: compact + buckets =================
__global__ void k5_build(const int* __restrict__ ei) {
    int tid = blockIdx.x * blockDim.x + threadIdx.x;
    int stride = gridDim.x * blockDim.x;
    for (int i = tid; i < NN; i += stride) {
        if (fl1[i]) { int j = atomicAdd(&g_cnt[0], 1); if (j < M1CAP) { lst1[j] = i; pos1[i] = j; } }
        if (fl2[i]) { int j = atomicAdd(&g_cnt[1], 1); if (j < M2CAP) { lst2[j] = i; pos2[i] = j; } }
    }
    for (int t = tid; t < ET; t += stride) {
        int s, d;
        if (t < EE) { s = ei[t]; d = ei[EE + t]; }
        else        { s = t - EE; d = t - EE; }
        if (fl1[d]) { int j = atomicAdd(&deg1[d], 1); if (j < DCAP) bk1[d * DCAP + j] = s; }
        if (fl2[d]) { int j = atomicAdd(&deg2[d], 1); if (j < DCAP) bk2[d * DCAP + j] = s; }
        if (fl3[d]) { int j = atomicAdd(&deg3[d], 1); if (j < DCAP) bk3[d * DCAP + j] = s; }
    }
}

// ================= gather: block per dst =================
// L1: computes layer-1 logits in-place from x (no precomputed es1).
// Zeroes C row (L1/L2) or preloads out row (L3). float4 feature path.
__global__ __launch_bounds__(256) void gatherK(int L, const float* __restrict__ x,
                                               const float* __restrict__ b1,
                                               const float* __restrict__ b2,
                                               const float* __restrict__ b3,
                                               float* __restrict__ out) {
    __shared__ float sLog[DCAP][HH];
    __shared__ float sEd[HH];
    __shared__ float sE[HH][DCAP];
    __shared__ int   sIdx[DCAP];
    __shared__ float sInv[HH];

    int M = (L == 1) ? g_cnt[0] : (L == 2) ? g_cnt[1] : 8;
    if (M > ((L == 1) ? M1CAP : (L == 2) ? M2CAP : 8)) M = (L == 1) ? M1CAP : (L == 2) ? M2CAP : 8;
    int KD = (L == 1) ? C0 : (L == 2) ? C1 : C2;
    int KD4 = KD >> 2;
    float slope = (L == 3) ? 0.f : 0.2f;
    int t = threadIdx.x, w = t >> 5, lane = t & 31;

    for (int i = blockIdx.x; i < M; i += gridDim.x) {
        if (L == 1) {
            for (int c = t; c < PITCH1; c += 256) C1g[(size_t)i * PITCH1 + c] = 0.f;
        } else if (L == 2) {
            for (int c = t; c < PITCH2; c += 256) C2g[(size_t)i * PITCH2 + c] = 0.f;
        } else {
            int node0 = nodeB[i];
            for (int c = t; c < C3; c += 256)
                out[i * C3 + c] = b3[c] + x[(size_t)node0 * C0 + c];
        }

        int node = (L == 1) ? lst1[i] : (L == 2) ? lst2[i] : nodeB[i];
        const int* bk = (L == 1) ? bk1 : (L == 2) ? bk2 : bk3;
        int dg = ((L == 1) ? deg1 : (L == 2) ? deg2 : deg3)[node];
        if (dg > DCAP) dg = DCAP;

        if (L == 1) {
            // phase A: per-edge src logits + dst logit; warp per item
            for (int item = w; item <= dg; item += 8) {
                int s = (item < dg) ? bk[node * DCAP + item] : node;
                const float* row = x + (size_t)s * C0;
                const float* pv = (item < dg) ? p1s : p1d;
                float a0 = 0.f, a1 = 0.f, a2 = 0.f, a3 = 0.f, a4 = 0.f, a5 = 0.f;
                for (int j = 0; j < 33; j++) {
                    int k = lane + j * 32;
                    if (k < C0) {
                        float xv = row[k];
                        a0 += xv * pv[0 * C0 + k];
                        a1 += xv * pv[1 * C0 + k];
                        a2 += xv * pv[2 * C0 + k];
                        a3 += xv * pv[3 * C0 + k];
                        a4 += xv * pv[4 * C0 + k];
                        a5 += xv * pv[5 * C0 + k];
                    }
                }
                #pragma unroll
                for (int o = 16; o > 0; o >>= 1) {
                    a0 += __shfl_down_sync(~0u, a0, o);
                    a1 += __shfl_down_sync(~0u, a1, o);
                    a2 += __shfl_down_sync(~0u, a2, o);
                    a3 += __shfl_down_sync(~0u, a3, o);
                    a4 += __shfl_down_sync(~0u, a4, o);
                    a5 += __shfl_down_sync(~0u, a5, o);
                }
                if (lane == 0) {
                    if (item < dg) {
                        sIdx[item] = s;
                        sLog[item][0] = a0; sLog[item][1] = a1; sLog[item][2] = a2;
                        sLog[item][3] = a3; sLog[item][4] = a4; sLog[item][5] = a5;
                    } else {
                        sEd[0] = a0; sEd[1] = a1; sEd[2] = a2;
                        sEd[3] = a3; sEd[4] = a4; sEd[5] = a5;
                    }
                }
            }
            __syncthreads();
            // phase B: softmax per head
            if (w < HH) {
                int h = w;
                float dl = sEd[h];
                float z = 0.f;
                for (int j = lane; j < dg; j += 32) {
                    float v = sLog[j][h] + dl;
                    v = (v >= 0.f) ? v : slope * v;
                    float e = __expf(v);
                    sE[h][j] = e;
                    z += e;
                }
                #pragma unroll
                for (int o = 16; o > 0; o >>= 1) z += __shfl_down_sync(~0u, z, o);
                if (lane == 0) sInv[h] = 1.0f / (6.0f * z);
            }
        } else {
            if (w < HH) {
                int h = w;
                float dl;
                if (L == 2) dl = C1g[(size_t)pos1[node] * PITCH1 + 134 + h] + c2d[h];
                else        dl = C2g[(size_t)pos2[node] * PITCH2 + 262 + h] + c3d[h];
                float z = 0.f;
                for (int j = lane; j < dg; j += 32) {
                    int s = bk[node * DCAP + j];
                    int si = (L == 2) ? pos1[s] : pos2[s];
                    if (h == 0) sIdx[j] = si;
                    float sl;
                    if (L == 2) sl = C1g[(size_t)si * PITCH1 + 128 + h] + c2s[h];
                    else        sl = C2g[(size_t)si * PITCH2 + 256 + h] + c3s[h];
                    float v = sl + dl;
                    v = (v >= 0.f) ? v : slope * v;
                    float e = __expf(v);
                    sE[h][j] = e;
                    z += e;
                }
                #pragma unroll
                for (int o = 16; o > 0; o >>= 1) z += __shfl_down_sync(~0u, z, o);
                if (lane == 0) sInv[h] = 1.0f / (6.0f * z);
            }
        }
        __syncthreads();

        // gather phase (float4)
        float* aggrow = (L == 1) ? (agg1 + (size_t)i * W3C)
                      : (L == 2) ? (agg2 + (size_t)i * 768)
                                 : (agg3 + (size_t)i * 1536);
        for (int kq = t; kq < KD4; kq += 256) {
            float4 bias4;
            if (L == 1)      bias4 = make_float4(0.f, 0.f, 0.f, 0.f);
            else if (L == 2) bias4 = ((const float4*)b1)[kq];
            else             bias4 = ((const float4*)b2)[kq];
            float4 a0 = {0,0,0,0}, a1 = {0,0,0,0}, a2 = {0,0,0,0};
            float4 a3 = {0,0,0,0}, a4 = {0,0,0,0}, a5 = {0,0,0,0};
            for (int j = 0; j < dg; j++) {
                float4 v;
                if (L == 1)      v = ((const float4*)(x + (size_t)sIdx[j] * C0))[kq];
                else if (L == 2) v = ((const float4*)(C1g + (size_t)sIdx[j] * PITCH1))[kq];
                else             v = ((const float4*)(C2g + (size_t)sIdx[j] * PITCH2))[kq];
                if (L != 1) { v.x += bias4.x; v.y += bias4.y; v.z += bias4.z; v.w += bias4.w; }
                float e;
                e = sE[0][j]; a0.x += e * v.x; a0.y += e * v.y; a0.z += e * v.z; a0.w += e * v.w;
                e = sE[1][j]; a1.x += e * v.x; a1.y += e * v.y; a1.z += e * v.z; a1.w += e * v.w;
                e = sE[2][j]; a2.x += e * v.x; a2.y += e * v.y; a2.z += e * v.z; a2.w += e * v.w;
                e = sE[3][j]; a3.x += e * v.x; a3.y += e * v.y; a3.z += e * v.z; a3.w += e * v.w;
                e = sE[4][j]; a4.x += e * v.x; a4.y += e * v.y; a4.z += e * v.z; a4.w += e * v.w;
                e = sE[5][j]; a5.x += e * v.x; a5.y += e * v.y; a5.z += e * v.z; a5.w += e * v.w;
            }
            float iv;
            iv = sInv[0]; a0.x *= iv; a0.y *= iv; a0.z *= iv; a0.w *= iv;
            iv = sInv[1]; a1.x *= iv; a1.y *= iv; a1.z *= iv; a1.w *= iv;
            iv = sInv[2]; a2.x *= iv; a2.y *= iv; a2.z *= iv; a2.w *= iv;
            iv = sInv[3]; a3.x *= iv; a3.y *= iv; a3.z *= iv; a3.w *= iv;
            iv = sInv[4]; a4.x *= iv; a4.y *= iv; a4.z *= iv; a4.w *= iv;
            iv = sInv[5]; a5.x *= iv; a5.y *= iv; a5.z *= iv; a5.w *= iv;
            ((float4*)(aggrow + 0 * KD))[kq] = a0;
            ((float4*)(aggrow + 1 * KD))[kq] = a1;
            ((float4*)(aggrow + 2 * KD))[kq] = a2;
            ((float4*)(aggrow + 3 * KD))[kq] = a3;
            ((float4*)(aggrow + 4 * KD))[kq] = a4;
            ((float4*)(aggrow + 5 * KD))[kq] = a5;
        }
        __syncthreads();
    }
}

// ================= gemm: C[M, N] += aggcat @ [Wcat | rS | rD] =================
__global__ __launch_bounds__(256) void gemmK(int L,
                                             const float* __restrict__ W1,
                                             const float* __restrict__ W2,
                                             const float* __restrict__ W3,
                                             float* __restrict__ out) {
    __shared__ float As[16][65];
    __shared__ float Bs[16][49];

    int M, Kcat, KD, WC, NW, Ncols, PITCH, KS, rStride;
    const float* A; const float* W; float* Cb; const float* rS; const float* rD;
    if (L == 1) {
        M = g_cnt[0]; if (M > M1CAP) M = M1CAP;
        Kcat = W3C; KD = C0; WC = W1C; NW = 128; Ncols = 140; PITCH = PITCH1; KS = 16;
        A = agg1; W = W1; Cb = C1g; rS = r2s; rD = r2d; rStride = W3C;
    } else if (L == 2) {
        M = g_cnt[1]; if (M > M2CAP) M = M2CAP;
        Kcat = 768; KD = C1; WC = W2C; NW = 256; Ncols = 268; PITCH = PITCH2; KS = 8;
        A = agg2; W = W2; Cb = C2g; rS = r3s; rD = r3d; rStride = 768;
    } else {
        M = 8;
        Kcat = 1536; KD = C2; WC = W3C; NW = 1028; Ncols = 1028; PITCH = 1028; KS = 8;
        A = agg3; W = W3; Cb = out; rS = r3s; rD = r3d; rStride = 768;
    }
    int rt = (M + 63) >> 6;
    int ct = (Ncols + 47) / 48;
    int nIter = (Kcat + 15) >> 4;
    int nt = rt * ct * KS;
    int t = threadIdx.x;
    int ty = t >> 4, tx = t & 15;

    for (int bid = blockIdx.x; bid < nt; bid += gridDim.x) {
        int ksl = bid % KS;
        int rest = bid / KS;
        int ctile = rest % ct, rtile = rest / ct;
        int row0 = rtile * 64, col0 = ctile * 48;
        int it0 = (int)(((long long)nIter * ksl) / KS);
        int it1 = (int)(((long long)nIter * (ksl + 1)) / KS);

        float acc[4][3];
        #pragma unroll
        for (int i = 0; i < 4; i++)
            #pragma unroll
            for (int j = 0; j < 3; j++) acc[i][j] = 0.f;

        for (int it = it0; it < it1; it++) {
            int kbase = it * 16;
            {
                int arow = t >> 2;
                int kq = (t & 3) * 4;
                int grow = row0 + arow;
                #pragma unroll
                for (int u = 0; u < 4; u++) {
                    int k = kbase + kq + u;
                    As[kq + u][arow] = (grow < M && k < Kcat) ? A[(size_t)grow * Kcat + k] : 0.f;
                }
            }
            {
                int bk = t >> 4;
                int cb = (t & 15) * 3;
                int K = kbase + bk;
                int head = 0, kk2 = 0;
                if (K < Kcat) { head = K / KD; kk2 = K - head * KD; }
                #pragma unroll
                for (int u = 0; u < 3; u++) {
                    int c = col0 + cb + u;
                    float val = 0.f;
                    if (K < Kcat && c < Ncols) {
                        if (c < NW)            val = W[(size_t)kk2 * WC + head * NW + c];
                        else if (c < NW + 6)   val = rS[(c - NW) * rStride + K];
                        else                   val = rD[(c - NW - 6) * rStride + K];
                    }
                    Bs[bk][cb + u] = val;
                }
            }
            __syncthreads();
            #pragma unroll
            for (int kk = 0; kk < 16; kk++) {
                float a0 = As[kk][ty * 4 + 0];
                float a1 = As[kk][ty * 4 + 1];
                float a2 = As[kk][ty * 4 + 2];
                float a3 = As[kk][ty * 4 + 3];
                float b0 = Bs[kk][tx * 3 + 0];
                float b1v = Bs[kk][tx * 3 + 1];
                float b2v = Bs[kk][tx * 3 + 2];
                acc[0][0] += a0 * b0; acc[0][1] += a0 * b1v; acc[0][2] += a0 * b2v;
                acc[1][0] += a1 * b0; acc[1][1] += a1 * b1v; acc[1][2] += a1 * b2v;
                acc[2][0] += a2 * b0; acc[2][1] += a2 * b1v; acc[2][2] += a2 * b2v;
                acc[3][0] += a3 * b0; acc[3][1] += a3 * b1v; acc[3][2] += a3 * b2v;
            }
            __syncthreads();
        }
        #pragma unroll
        for (int i = 0; i < 4; i++) {
            int r = row0 + ty * 4 + i;
            if (r < M) {
                #pragma unroll
                for (int j = 0; j < 3; j++) {
                    int c = col0 + tx * 3 + j;
                    if (c < Ncols) atomicAdd(&Cb[(size_t)r * PITCH + c], acc[i][j]);
                }
            }
        }
    }
}

// ---------------- launch ----------------
extern "C" void kernel_launch(void* const* d_in, const int* in_sizes, int n_in,
                              void* d_out, int out_size) {
    const float* x   = (const float*)d_in[0];
    const int*   ei  = (const int*)d_in[1];
    const int*   ptr = (const int*)d_in[2];
    const float* W1  = (const float*)d_in[3];
    const float* as1 = (const float*)d_in[4];
    const float* ad1 = (const float*)d_in[5];
    const float* b1  = (const float*)d_in[6];
    const float* W2  = (const float*)d_in[7];
    const float* as2 = (const float*)d_in[8];
    const float* ad2 = (const float*)d_in[9];
    const float* b2  = (const float*)d_in[10];
    const float* W3  = (const float*)d_in[11];
    const float* as3 = (const float*)d_in[12];
    const float* ad3 = (const float*)d_in[13];
    const float* b3  = (const float*)d_in[14];
    float* out = (float*)d_out;

    k1_init<<<512, 256>>>(W1, as1, ad1, W2, as2, ad2, W3, as3, ad3);
    k2_expand3<<<512, 256>>>(ei, ptr, W1, W2, b1, b2);
    k3_expand2<<<128, 256>>>(ei);
    k5_build<<<1024, 256>>>(ei);
    gatherK<<<512, 256>>>(1, x, b1, b2, b3, out);
    gemmK<<<192, 256>>>(1, W1, W2, W3, out);
    gatherK<<<64, 256>>>(2, x, b1, b2, b3, out);
    gemmK<<<64, 256>>>(2, W1, W2, W3, out);
    gatherK<<<16, 256>>>(3, x, b1, b2, b3, out);
    gemmK<<<192, 256>>>(3, W1, W2, W3, out);
}

// round 16
// speedup vs baseline: 3.1475x; 1.2714x over previous
#include <cuda_runtime.h>
#include <math.h>

// GAT_15547781612261 — round 16: 9 kernels. r-vectors eliminated (logits computed
// in each gather from p·(h+b)); k1+k2 merged (flag zeroing moved to gemm3 tail,
// first run relies on load-time zero-init of __device__ globals).

#define NN 8192
#define EE 32768
#define ET (EE + NN)
#define HH 6
#define DCAP 64
#define M1CAP 8192
#define M2CAP 2048

#define C0 1028
#define C1 128
#define C2 256
#define C3 1028
#define W1C 768
#define W2C 1536
#define W3C 6168
#define PITCH1 128
#define PITCH2 256

// ---------------- device globals (zero-initialized at load; re-zeroed by gemm3 tail) ----------------
__device__ int fl1[NN], fl2[NN], fl3[NN];
__device__ int pos1[NN], pos2[NN];
__device__ int lst1[M1CAP], lst2[M2CAP];
__device__ int g_cnt[4];
__device__ int nodeB[8];
__device__ int deg1[NN], deg2[NN], deg3[NN];
__device__ int bk1[NN * DCAP], bk2[NN * DCAP], bk3[NN * DCAP];
__device__ float p1s[HH * C0], p1d[HH * C0];
__device__ float p2s[HH * C1], p2d[HH * C1];
__device__ float p3s[HH * C2], p3d[HH * C2];
__device__ float agg1[(size_t)M1CAP * W3C];
__device__ float agg2[(size_t)M2CAP * 768];
__device__ float agg3[8 * 1536];
__device__ float C1g[(size_t)M1CAP * PITCH1];    // h1 (bias NOT folded)
__device__ float C2g[(size_t)M2CAP * PITCH2];    // h2 (bias NOT folded)

// ================= kA: mark + expand3 + p-vectors (no zeroing needed) =================
__global__ void kA_init(const int* __restrict__ ei, const int* __restrict__ ptr,
                        const float* __restrict__ W1, const float* __restrict__ as1, const float* __restrict__ ad1,
                        const float* __restrict__ W2, const float* __restrict__ as2, const float* __restrict__ ad2,
                        const float* __restrict__ W3, const float* __restrict__ as3, const float* __restrict__ ad3) {
    int tid = blockIdx.x * blockDim.x + threadIdx.x;
    int stride = gridDim.x * blockDim.x;
    if (tid < 8) {
        int node = ptr[tid + 1] - 1;
        nodeB[tid] = node;
        fl3[node] = 1; fl2[node] = 1; fl1[node] = 1;
    }
    int t1 = ptr[1] - 1, t2 = ptr[2] - 1, t3 = ptr[3] - 1, t4 = ptr[4] - 1;
    int t5 = ptr[5] - 1, t6 = ptr[6] - 1, t7 = ptr[7] - 1, t8 = ptr[8] - 1;
    for (int e = tid; e < EE; e += stride) {
        int d = ei[EE + e];
        if (d == t1 || d == t2 || d == t3 || d == t4 || d == t5 || d == t6 || d == t7 || d == t8) {
            int s = ei[e];
            fl2[s] = 1; fl1[s] = 1;
        }
    }
    int w = tid >> 5, lane = tid & 31, nw = stride >> 5;
    for (int it = w; it < HH * C0; it += nw) {
        int h = it % HH, k = it / HH;
        const float* wr = W1 + (size_t)k * W1C + h * C1;
        const float* va = as1 + h * C1;
        const float* vd = ad1 + h * C1;
        float ss = 0.f, sd = 0.f;
        #pragma unroll
        for (int j = 0; j < C1 / 32; j++) {
            int c = lane + j * 32;
            float wv = wr[c];
            ss += wv * va[c]; sd += wv * vd[c];
        }
        #pragma unroll
        for (int o = 16; o > 0; o >>= 1) { ss += __shfl_down_sync(~0u, ss, o); sd += __shfl_down_sync(~0u, sd, o); }
        if (lane == 0) { p1s[h * C0 + k] = ss; p1d[h * C0 + k] = sd; }
    }
    for (int it = w; it < HH * C1; it += nw) {
        int h = it % HH, k = it / HH;
        const float* wr = W2 + (size_t)k * W2C + h * C2;
        const float* va = as2 + h * C2;
        const float* vd = ad2 + h * C2;
        float ss = 0.f, sd = 0.f;
        #pragma unroll
        for (int j = 0; j < C2 / 32; j++) {
            int c = lane + j * 32;
            float wv = wr[c];
            ss += wv * va[c]; sd += wv * vd[c];
        }
        #pragma unroll
        for (int o = 16; o > 0; o >>= 1) { ss += __shfl_down_sync(~0u, ss, o); sd += __shfl_down_sync(~0u, sd, o); }
        if (lane == 0) { p2s[h * C1 + k] = ss; p2d[h * C1 + k] = sd; }
    }
    for (int it = w; it < HH * C2; it += nw) {
        int h = it % HH, k = it / HH;
        const float* wr = W3 + (size_t)k * W3C + h * C3;
        const float* va = as3 + h * C3;
        const float* vd = ad3 + h * C3;
        float ss = 0.f, sd = 0.f;
        for (int j = 0; j < 33; j++) {
            int c = lane + j * 32;
            if (c < C3) { float wv = wr[c]; ss += wv * va[c]; sd += wv * vd[c]; }
        }
        #pragma unroll
        for (int o = 16; o > 0; o >>= 1) { ss += __shfl_down_sync(~0u, ss, o); sd += __shfl_down_sync(~0u, sd, o); }
        if (lane == 0) { p3s[h * C2 + k] = ss; p3d[h * C2 + k] = sd; }
    }
}

// ================= k3: expand level 2 =================
__global__ void k3_expand2(const int* __restrict__ ei) {
    int tid = blockIdx.x * blockDim.x + threadIdx.x;
    int stride = gridDim.x * blockDim.x;
    for (int e = tid; e < EE; e += stride) {
        int d = ei[EE + e];
        if (fl2[d]) fl1[ei[e]] = 1;
    }
}

// ================= k5: compact + buckets =================
__global__ void k5_build(const int* __restrict__ ei) {
    int tid = blockIdx.x * blockDim.x + threadIdx.x;
    int stride = gridDim.x * blockDim.x;
    for (int i = tid; i < NN; i += stride) {
        if (fl1[i]) { int j = atomicAdd(&g_cnt[0], 1); if (j < M1CAP) { lst1[j] = i; pos1[i] = j; } }
        if (fl2[i]) { int j = atomicAdd(&g_cnt[1], 1); if (j < M2CAP) { lst2[j] = i; pos2[i] = j; } }
    }
    for (int t = tid; t < ET; t += stride) {
        int s, d;
        if (t < EE) { s = ei[t]; d = ei[EE + t]; }
        else        { s = t - EE; d = t - EE; }
        if (fl1[d]) { int j = atomicAdd(&deg1[d], 1); if (j < DCAP) bk1[d * DCAP + j] = s; }
        if (fl2[d]) { int j = atomicAdd(&deg2[d], 1); if (j < DCAP) bk2[d * DCAP + j] = s; }
        if (fl3[d]) { int j = atomicAdd(&deg3[d], 1); if (j < DCAP) bk3[d * DCAP + j] = s; }
    }
}

// ================= gather: block per dst; logits computed in-kernel =================
// L1: logits from x·p1 ; L2: (C1g+b1)·p2 ; L3: (C2g+b2)·p3.
// Zeroes C row (L1/L2) or preloads out row (L3). float4 feature path.
__global__ __launch_bounds__(256) void gatherK(int L, const float* __restrict__ x,
                                               const float* __restrict__ b1,
                                               const float* __restrict__ b2,
                                               const float* __restrict__ b3,
                                               float* __restrict__ out) {
    __shared__ float sLog[DCAP][HH];
    __shared__ float sEd[HH];
    __shared__ float sE[HH][DCAP];
    __shared__ int   sIdx[DCAP];
    __shared__ float sInv[HH];

    int M = (L == 1) ? g_cnt[0] : (L == 2) ? g_cnt[1] : 8;
    if (M > ((L == 1) ? M1CAP : (L == 2) ? M2CAP : 8)) M = (L == 1) ? M1CAP : (L == 2) ? M2CAP : 8;
    int KD = (L == 1) ? C0 : (L == 2) ? C1 : C2;
    int KD4 = KD >> 2;
    float slope = (L == 3) ? 0.f : 0.2f;
    int t = threadIdx.x, w = t >> 5, lane = t & 31;

    for (int i = blockIdx.x; i < M; i += gridDim.x) {
        if (L == 1) {
            for (int c = t; c < PITCH1; c += 256) C1g[(size_t)i * PITCH1 + c] = 0.f;
        } else if (L == 2) {
            for (int c = t; c < PITCH2; c += 256) C2g[(size_t)i * PITCH2 + c] = 0.f;
        } else {
            int node0 = nodeB[i];
            for (int c = t; c < C3; c += 256)
                out[i * C3 + c] = b3[c] + x[(size_t)node0 * C0 + c];
        }

        int node = (L == 1) ? lst1[i] : (L == 2) ? lst2[i] : nodeB[i];
        const int* bk = (L == 1) ? bk1 : (L == 2) ? bk2 : bk3;
        int dg = ((L == 1) ? deg1 : (L == 2) ? deg2 : deg3)[node];
        if (dg > DCAP) dg = DCAP;

        // phase A: warp per item (dg srcs + 1 dst); dot(feature_row, p-vector)
        for (int item = w; item <= dg; item += 8) {
            bool isDst = (item == dg);
            int s_node = isDst ? node : bk[node * DCAP + item];
            const float* row;
            int storeIdx;
            if (L == 1)      { row = x + (size_t)s_node * C0;             storeIdx = s_node; }
            else if (L == 2) { int si = pos1[s_node]; row = C1g + (size_t)si * PITCH1; storeIdx = si; }
            else             { int si = pos2[s_node]; row = C2g + (size_t)si * PITCH2; storeIdx = si; }
            const float* pv = isDst ? ((L == 1) ? p1d : (L == 2) ? p2d : p3d)
                                    : ((L == 1) ? p1s : (L == 2) ? p2s : p3s);
            float a0 = 0.f, a1 = 0.f, a2 = 0.f, a3 = 0.f, a4 = 0.f, a5 = 0.f;
            if (L == 1) {
                for (int j = 0; j < 33; j++) {
                    int k = lane + j * 32;
                    if (k < C0) {
                        float xv = row[k];
                        a0 += xv * pv[0 * C0 + k];
                        a1 += xv * pv[1 * C0 + k];
                        a2 += xv * pv[2 * C0 + k];
                        a3 += xv * pv[3 * C0 + k];
                        a4 += xv * pv[4 * C0 + k];
                        a5 += xv * pv[5 * C0 + k];
                    }
                }
            } else {
                const float* bias = (L == 2) ? b1 : b2;
                for (int k = lane; k < KD; k += 32) {
                    float xv = row[k] + bias[k];
                    a0 += xv * pv[0 * KD + k];
                    a1 += xv * pv[1 * KD + k];
                    a2 += xv * pv[2 * KD + k];
                    a3 += xv * pv[3 * KD + k];
                    a4 += xv * pv[4 * KD + k];
                    a5 += xv * pv[5 * KD + k];
                }
            }
            #pragma unroll
            for (int o = 16; o > 0; o >>= 1) {
                a0 += __shfl_down_sync(~0u, a0, o);
                a1 += __shfl_down_sync(~0u, a1, o);
                a2 += __shfl_down_sync(~0u, a2, o);
                a3 += __shfl_down_sync(~0u, a3, o);
                a4 += __shfl_down_sync(~0u, a4, o);
                a5 += __shfl_down_sync(~0u, a5, o);
            }
            if (lane == 0) {
                if (!isDst) {
                    sIdx[item] = storeIdx;
                    sLog[item][0] = a0; sLog[item][1] = a1; sLog[item][2] = a2;
                    sLog[item][3] = a3; sLog[item][4] = a4; sLog[item][5] = a5;
                } else {
                    sEd[0] = a0; sEd[1] = a1; sEd[2] = a2;
                    sEd[3] = a3; sEd[4] = a4; sEd[5] = a5;
                }
            }
        }
        __syncthreads();
        // phase B: softmax per head
        if (w < HH) {
            int h = w;
            float dl = sEd[h];
            float z = 0.f;
            for (int j = lane; j < dg; j += 32) {
                float v = sLog[j][h] + dl;
                v = (v >= 0.f) ? v : slope * v;
                float e = __expf(v);
                sE[h][j] = e;
                z += e;
            }
            #pragma unroll
            for (int o = 16; o > 0; o >>= 1) z += __shfl_down_sync(~0u, z, o);
            if (lane == 0) sInv[h] = 1.0f / (6.0f * z);
        }
        __syncthreads();

        // gather phase (float4)
        float* aggrow = (L == 1) ? (agg1 + (size_t)i * W3C)
                      : (L == 2) ? (agg2 + (size_t)i * 768)
                                 : (agg3 + (size_t)i * 1536);
        for (int kq = t; kq < KD4; kq += 256) {
            float4 bias4;
            if (L == 1)      bias4 = make_float4(0.f, 0.f, 0.f, 0.f);
            else if (L == 2) bias4 = ((const float4*)b1)[kq];
            else             bias4 = ((const float4*)b2)[kq];
            float4 a0 = {0,0,0,0}, a1 = {0,0,0,0}, a2 = {0,0,0,0};
            float4 a3 = {0,0,0,0}, a4 = {0,0,0,0}, a5 = {0,0,0,0};
            for (int j = 0; j < dg; j++) {
                float4 v;
                if (L == 1)      v = ((const float4*)(x + (size_t)sIdx[j] * C0))[kq];
                else if (L == 2) v = ((const float4*)(C1g + (size_t)sIdx[j] * PITCH1))[kq];
                else             v = ((const float4*)(C2g + (size_t)sIdx[j] * PITCH2))[kq];
                if (L != 1) { v.x += bias4.x; v.y += bias4.y; v.z += bias4.z; v.w += bias4.w; }
                float e;
                e = sE[0][j]; a0.x += e * v.x; a0.y += e * v.y; a0.z += e * v.z; a0.w += e * v.w;
                e = sE[1][j]; a1.x += e * v.x; a1.y += e * v.y; a1.z += e * v.z; a1.w += e * v.w;
                e = sE[2][j]; a2.x += e * v.x; a2.y += e * v.y; a2.z += e * v.z; a2.w += e * v.w;
                e = sE[3][j]; a3.x += e * v.x; a3.y += e * v.y; a3.z += e * v.z; a3.w += e * v.w;
                e = sE[4][j]; a4.x += e * v.x; a4.y += e * v.y; a4.z += e * v.z; a4.w += e * v.w;
                e = sE[5][j]; a5.x += e * v.x; a5.y += e * v.y; a5.z += e * v.z; a5.w += e * v.w;
            }
            float iv;
            iv = sInv[0]; a0.x *= iv; a0.y *= iv; a0.z *= iv; a0.w *= iv;
            iv = sInv[1]; a1.x *= iv; a1.y *= iv; a1.z *= iv; a1.w *= iv;
            iv = sInv[2]; a2.x *= iv; a2.y *= iv; a2.z *= iv; a2.w *= iv;
            iv = sInv[3]; a3.x *= iv; a3.y *= iv; a3.z *= iv; a3.w *= iv;
            iv = sInv[4]; a4.x *= iv; a4.y *= iv; a4.z *= iv; a4.w *= iv;
            iv = sInv[5]; a5.x *= iv; a5.y *= iv; a5.z *= iv; a5.w *= iv;
            ((float4*)(aggrow + 0 * KD))[kq] = a0;
            ((float4*)(aggrow + 1 * KD))[kq] = a1;
            ((float4*)(aggrow + 2 * KD))[kq] = a2;
            ((float4*)(aggrow + 3 * KD))[kq] = a3;
            ((float4*)(aggrow + 4 * KD))[kq] = a4;
            ((float4*)(aggrow + 5 * KD))[kq] = a5;
        }
        __syncthreads();
    }
}

// ================= gemm: C[M, N] += aggcat @ Wcat =================
// BM=64, BN=48, BK=16, 256 threads, 4x3 microtile, K-split via atomicAdd.
// L3 additionally re-zeroes flags/deg/g_cnt for the next replay.
__global__ __launch_bounds__(256) void gemmK(int L,
                                             const float* __restrict__ W1,
                                             const float* __restrict__ W2,
                                             const float* __restrict__ W3,
                                             float* __restrict__ out) {
    __shared__ float As[16][65];
    __shared__ float Bs[16][49];

    int M, Kcat, KD, WC, NW, PITCH, KS;
    const float* A; const float* W; float* Cb;
    if (L == 1) {
        M = g_cnt[0]; if (M > M1CAP) M = M1CAP;
        Kcat = W3C; KD = C0; WC = W1C; NW = 128; PITCH = PITCH1; KS = 16;
        A = agg1; W = W1; Cb = C1g;
    } else if (L == 2) {
        M = g_cnt[1]; if (M > M2CAP) M = M2CAP;
        Kcat = 768; KD = C1; WC = W2C; NW = 256; PITCH = PITCH2; KS = 8;
        A = agg2; W = W2; Cb = C2g;
    } else {
        M = 8;
        Kcat = 1536; KD = C2; WC = W3C; NW = 1028; PITCH = 1028; KS = 8;
        A = agg3; W = W3; Cb = out;
    }
    int Ncols = NW;
    int rt = (M + 63) >> 6;
    int ct = (Ncols + 47) / 48;
    int nIter = (Kcat + 15) >> 4;
    int nt = rt * ct * KS;
    int t = threadIdx.x;
    int ty = t >> 4, tx = t & 15;

    for (int bid = blockIdx.x; bid < nt; bid += gridDim.x) {
        int ksl = bid % KS;
        int rest = bid / KS;
        int ctile = rest % ct, rtile = rest / ct;
        int row0 = rtile * 64, col0 = ctile * 48;
        int it0 = (int)(((long long)nIter * ksl) / KS);
        int it1 = (int)(((long long)nIter * (ksl + 1)) / KS);

        float acc[4][3];
        #pragma unroll
        for (int i = 0; i < 4; i++)
            #pragma unroll
            for (int j = 0; j < 3; j++) acc[i][j] = 0.f;

        for (int it = it0; it < it1; it++) {
            int kbase = it * 16;
            {
                int arow = t >> 2;
                int kq = (t & 3) * 4;
                int grow = row0 + arow;
                #pragma unroll
                for (int u = 0; u < 4; u++) {
                    int k = kbase + kq + u;
                    As[kq + u][arow] = (grow < M && k < Kcat) ? A[(size_t)grow * Kcat + k] : 0.f;
                }
            }
            {
                int bk = t >> 4;
                int cb = (t & 15) * 3;
                int K = kbase + bk;
                int head = 0, kk2 = 0;
                if (K < Kcat) { head = K / KD; kk2 = K - head * KD; }
                #pragma unroll
                for (int u = 0; u < 3; u++) {
                    int c = col0 + cb + u;
                    float val = 0.f;
                    if (K < Kcat && c < Ncols) val = W[(size_t)kk2 * WC + head * NW + c];
                    Bs[bk][cb + u] = val;
                }
            }
            __syncthreads();
            #pragma unroll
            for (int kk = 0; kk < 16; kk++) {
                float a0 = As[kk][ty * 4 + 0];
                float a1 = As[kk][ty * 4 + 1];
                float a2 = As[kk][ty * 4 + 2];
                float a3 = As[kk][ty * 4 + 3];
                float b0 = Bs[kk][tx * 3 + 0];
                float b1v = Bs[kk][tx * 3 + 1];
                float b2v = Bs[kk][tx * 3 + 2];
                acc[0][0] += a0 * b0; acc[0][1] += a0 * b1v; acc[0][2] += a0 * b2v;
                acc[1][0] += a1 * b0; acc[1][1] += a1 * b1v; acc[1][2] += a1 * b2v;
                acc[2][0] += a2 * b0; acc[2][1] += a2 * b1v; acc[2][2] += a2 * b2v;
                acc[3][0] += a3 * b0; acc[3][1] += a3 * b1v; acc[3][2] += a3 * b2v;
            }
            __syncthreads();
        }
        #pragma unroll
        for (int i = 0; i < 4; i++) {
            int r = row0 + ty * 4 + i;
            if (r < M) {
                #pragma unroll
                for (int j = 0; j < 3; j++) {
                    int c = col0 + tx * 3 + j;
                    if (c < Ncols) atomicAdd(&Cb[(size_t)r * PITCH + c], acc[i][j]);
                }
            }
        }
    }

    // L3 tail: restore zeroed graph state for the next replay (deterministic)
    if (L == 3) {
        int gtid = blockIdx.x * 256 + t;
        int gstride = gridDim.x * 256;
        for (int i = gtid; i < NN; i += gstride) {
            fl1[i] = 0; fl2[i] = 0; fl3[i] = 0;
            deg1[i] = 0; deg2[i] = 0; deg3[i] = 0;
        }
        if (gtid < 4) g_cnt[gtid] = 0;
    }
}

// ---------------- launch ----------------
extern "C" void kernel_launch(void* const* d_in, const int* in_sizes, int n_in,
                              void* d_out, int out_size) {
    const float* x   = (const float*)d_in[0];
    const int*   ei  = (const int*)d_in[1];
    const int*   ptr = (const int*)d_in[2];
    const float* W1  = (const float*)d_in[3];
    const float* as1 = (const float*)d_in[4];
    const float* ad1 = (const float*)d_in[5];
    const float* b1  = (const float*)d_in[6];
    const float* W2  = (const float*)d_in[7];
    const float* as2 = (const float*)d_in[8];
    const float* ad2 = (const float*)d_in[9];
    const float* b2  = (const float*)d_in[10];
    const float* W3  = (const float*)d_in[11];
    const float* as3 = (const float*)d_in[12];
    const float* ad3 = (const float*)d_in[13];
    const float* b3  = (const float*)d_in[14];
    float* out = (float*)d_out;

    kA_init<<<512, 256>>>(ei, ptr, W1, as1, ad1, W2, as2, ad2, W3, as3, ad3);
    k3_expand2<<<128, 256>>>(ei);
    k5_build<<<1024, 256>>>(ei);
    gatherK<<<512, 256>>>(1, x, b1, b2, b3, out);
    gemmK<<<192, 256>>>(1, W1, W2, W3, out);
    gatherK<<<64, 256>>>(2, x, b1, b2, b3, out);
    gemmK<<<64, 256>>>(2, W1, W2, W3, out);
    gatherK<<<16, 256>>>(3, x, b1, b2, b3, out);
    gemmK<<<192, 256>>>(3, W1, W2, W3, out);
}